// round 3
// baseline (speedup 1.0000x reference)
#include <cuda_runtime.h>

// MultiHeadAttentionMap: B=2, S=2048, D=1024, H=16, head_dim=64
// Flash-attention style single-pass kernel, fp32 SIMT baseline.
// R3: mask is int32 (harness promotes bool), converted to float bias tile.

#define BM 64          // query tile rows
#define BN 64          // key tile cols
#define HD 64          // head dim
#define SSTR 65        // padded smem stride (floats) to avoid bank conflicts
#define NTHREADS 256

static constexpr int Bc = 2, Sc = 2048, Dc = 1024, Hc = 16;
// Q,K,V,P padded tiles + float bias tile
static constexpr int SMEM_BYTES = (4 * BM * SSTR) * 4 + BM * BN * 4;

__global__ void __launch_bounds__(NTHREADS)
mha_fwd(const float* __restrict__ Q, const float* __restrict__ K,
        const float* __restrict__ V, const int* __restrict__ Mask,
        float* __restrict__ Out)
{
    extern __shared__ float smem[];
    float* Qs = smem;                       // [BM][SSTR]
    float* Ks = Qs + BM * SSTR;             // [BN][SSTR]
    float* Vs = Ks + BN * SSTR;             // [BN][SSTR]
    float* Ps = Vs + BN * SSTR;             // [BM][SSTR]
    float* Bs = Ps + BM * SSTR;             // [BM][BN] bias (0 or -1e9)

    const int tid = threadIdx.x;
    const int qt = blockIdx.x;
    const int h  = blockIdx.y;
    const int b  = blockIdx.z;
    const int q0 = qt * BM;

    const int rg = tid >> 4;    // 0..15 : row group (4 rows each)
    const int cg = tid & 15;    // 0..15 : col group (4 cols each)
    const int r0 = rg * 4;
    const int c0 = cg * 4;

    // ---- load Q tile (persistent) ----
    const float* qbase = Q + ((size_t)b * Sc + q0) * Dc + h * HD;
    #pragma unroll
    for (int i = tid; i < BM * (HD / 4); i += NTHREADS) {
        int r = i >> 4, d4 = (i & 15) << 2;
        float4 t = *(const float4*)(qbase + (size_t)r * Dc + d4);
        float* dst = Qs + r * SSTR + d4;
        dst[0] = t.x; dst[1] = t.y; dst[2] = t.z; dst[3] = t.w;
    }

    float m_i[4], l_i[4], o[4][4];
    #pragma unroll
    for (int i = 0; i < 4; i++) {
        m_i[i] = -1e30f; l_i[i] = 0.f;
        #pragma unroll
        for (int j = 0; j < 4; j++) o[i][j] = 0.f;
    }

    const float* kbase = K + ((size_t)b * Sc) * Dc + h * HD;
    const float* vbase = V + ((size_t)b * Sc) * Dc + h * HD;
    const int* mbase = Mask + ((size_t)b * Sc + q0) * Sc;
    const float scale = 0.125f;  // 1/sqrt(64)

    for (int kt = 0; kt < Sc / BN; ++kt) {
        const int k0 = kt * BN;
        __syncthreads();   // prior GEMMs done reading Ks/Vs/Ps

        // ---- load K, V tiles ----
        for (int i = tid; i < BN * (HD / 4); i += NTHREADS) {
            int r = i >> 4, d4 = (i & 15) << 2;
            float4 tk = *(const float4*)(kbase + (size_t)(k0 + r) * Dc + d4);
            float4 tv = *(const float4*)(vbase + (size_t)(k0 + r) * Dc + d4);
            float* dk = Ks + r * SSTR + d4;
            dk[0] = tk.x; dk[1] = tk.y; dk[2] = tk.z; dk[3] = tk.w;
            float* dv = Vs + r * SSTR + d4;
            dv[0] = tv.x; dv[1] = tv.y; dv[2] = tv.z; dv[3] = tv.w;
        }
        // ---- load mask tile (int32) -> float bias tile ----
        // 64x64 ints = 1024 int4 loads; 256 threads x 4 int4 each
        #pragma unroll
        for (int u = 0; u < 4; ++u) {
            int idx = tid + u * NTHREADS;          // 0..1023, each = one int4
            int r = idx >> 4, c4 = (idx & 15) << 2;
            int4 tm = *(const int4*)(mbase + (size_t)r * Sc + k0 + c4);
            float4 fb;
            fb.x = tm.x ? 0.f : -1.0e9f;
            fb.y = tm.y ? 0.f : -1.0e9f;
            fb.z = tm.z ? 0.f : -1.0e9f;
            fb.w = tm.w ? 0.f : -1.0e9f;
            *(float4*)(Bs + r * BN + c4) = fb;
        }
        __syncthreads();

        // ---- GEMM1: S = Q @ K^T (4x4 per thread) ----
        float s[4][4];
        #pragma unroll
        for (int i = 0; i < 4; i++)
            #pragma unroll
            for (int j = 0; j < 4; j++) s[i][j] = 0.f;

        #pragma unroll 16
        for (int d = 0; d < HD; ++d) {
            float a[4], bb[4];
            #pragma unroll
            for (int i = 0; i < 4; i++) a[i] = Qs[(r0 + i) * SSTR + d];
            #pragma unroll
            for (int j = 0; j < 4; j++) bb[j] = Ks[(c0 + j) * SSTR + d];
            #pragma unroll
            for (int i = 0; i < 4; i++)
                #pragma unroll
                for (int j = 0; j < 4; j++)
                    s[i][j] = fmaf(a[i], bb[j], s[i][j]);
        }

        // ---- scale + mask + online softmax ----
        float rmax[4], rsum[4];
        #pragma unroll
        for (int i = 0; i < 4; i++) {
            rmax[i] = -1e30f;
            #pragma unroll
            for (int j = 0; j < 4; j++) {
                float sv = s[i][j] * scale + Bs[(r0 + i) * BN + (c0 + j)];
                s[i][j] = sv;
                rmax[i] = fmaxf(rmax[i], sv);
            }
        }
        // reduce max across the 16 threads sharing these rows
        #pragma unroll
        for (int off = 8; off >= 1; off >>= 1)
            #pragma unroll
            for (int i = 0; i < 4; i++)
                rmax[i] = fmaxf(rmax[i], __shfl_xor_sync(0xffffffffu, rmax[i], off));

        float m_new[4], alpha[4];
        #pragma unroll
        for (int i = 0; i < 4; i++) {
            m_new[i] = fmaxf(m_i[i], rmax[i]);
            alpha[i] = __expf(m_i[i] - m_new[i]);
            rsum[i] = 0.f;
            #pragma unroll
            for (int j = 0; j < 4; j++) {
                float p = __expf(s[i][j] - m_new[i]);
                s[i][j] = p;
                rsum[i] += p;
            }
        }
        #pragma unroll
        for (int off = 8; off >= 1; off >>= 1)
            #pragma unroll
            for (int i = 0; i < 4; i++)
                rsum[i] += __shfl_xor_sync(0xffffffffu, rsum[i], off);

        #pragma unroll
        for (int i = 0; i < 4; i++) {
            l_i[i] = l_i[i] * alpha[i] + rsum[i];
            m_i[i] = m_new[i];
            #pragma unroll
            for (int j = 0; j < 4; j++) {
                o[i][j] *= alpha[i];
                Ps[(r0 + i) * SSTR + (c0 + j)] = s[i][j];
            }
        }
        __syncthreads();   // P tile fully written before any thread reads full rows

        // ---- GEMM2: O += P @ V (4x4 per thread) ----
        #pragma unroll 16
        for (int c = 0; c < BN; ++c) {
            float a[4], bb[4];
            #pragma unroll
            for (int i = 0; i < 4; i++) a[i] = Ps[(r0 + i) * SSTR + c];
            #pragma unroll
            for (int j = 0; j < 4; j++) bb[j] = Vs[c * SSTR + (c0 + j)];
            #pragma unroll
            for (int i = 0; i < 4; i++)
                #pragma unroll
                for (int j = 0; j < 4; j++)
                    o[i][j] = fmaf(a[i], bb[j], o[i][j]);
        }
    }

    // ---- normalize and write out: out[b, q0+r, h*64 + c] ----
    float* obase = Out + ((size_t)b * Sc + q0) * Dc + h * HD;
    #pragma unroll
    for (int i = 0; i < 4; i++) {
        float inv = 1.f / l_i[i];
        float4 t;
        t.x = o[i][0] * inv; t.y = o[i][1] * inv;
        t.z = o[i][2] * inv; t.w = o[i][3] * inv;
        *(float4*)(obase + (size_t)(r0 + i) * Dc + c0) = t;
    }
}

extern "C" void kernel_launch(void* const* d_in, const int* in_sizes, int n_in,
                              void* d_out, int out_size)
{
    const float* q = (const float*)d_in[0];
    const float* k = (const float*)d_in[1];
    const float* v = (const float*)d_in[2];
    const int* mask = (const int*)d_in[3];
    float* out = (float*)d_out;

    cudaFuncSetAttribute(mha_fwd, cudaFuncAttributeMaxDynamicSharedMemorySize, SMEM_BYTES);

    dim3 grid(Sc / BM, Hc, Bc);
    mha_fwd<<<grid, NTHREADS, SMEM_BYTES>>>(q, k, v, mask, out);
}

// round 5
// speedup vs baseline: 2.1286x; 2.1286x over previous
#include <cuda_runtime.h>
#include <cuda_bf16.h>
#include <cstdint>

// MultiHeadAttentionMap: B=2, S=2048, D=1024, H=16, head_dim=64
// R5: mma.sync (HMMA bf16, base ISA) flash attention, 2-term bf16 splits.
// tcgen05 unavailable: harness compiles via compute_103 (no 'a' features).

#define S_LEN 2048
#define DMODEL 1024
#define NHEAD 16
#define BATCH 2
#define HD 64
#define BM 128          // rows per CTA (8 warps x 16)
#define BN 64           // keys per tile
#define NKT (S_LEN / BN)
#define NTH 256

// smem: K/V tiles, bf16 hi/lo, [64 rows][72 cols] (144B stride, conflict-free ldmatrix)
#define ROWB 144
#define TILE_B (64 * ROWB)   // 9216

__device__ __align__(8) unsigned g_mbits[BATCH * S_LEN * S_LEN / 32];

__device__ __forceinline__ uint32_t smem_u32(const void* p) {
    uint32_t a;
    asm("{ .reg .u64 t; cvta.to.shared.u64 t, %1; cvt.u32.u64 %0, t; }" : "=r"(a) : "l"(p));
    return a;
}
// pack two fp32 -> bf16x2 reg, lo = first element (lower k index)
__device__ __forceinline__ uint32_t pack2(float lo, float hi) {
    uint32_t d;
    asm("cvt.rn.bf16x2.f32 %0, %1, %2;" : "=r"(d) : "f"(hi), "f"(lo));
    return d;
}
__device__ __forceinline__ float tobf(float f) {
    return __bfloat162float(__float2bfloat16_rn(f));
}
__device__ __forceinline__ void mma_bf16(float* c, const uint32_t* a, uint32_t b0, uint32_t b1) {
    asm volatile(
        "mma.sync.aligned.m16n8k16.row.col.f32.bf16.bf16.f32 "
        "{%0,%1,%2,%3}, {%4,%5,%6,%7}, {%8,%9}, {%0,%1,%2,%3};"
        : "+f"(c[0]), "+f"(c[1]), "+f"(c[2]), "+f"(c[3])
        : "r"(a[0]), "r"(a[1]), "r"(a[2]), "r"(a[3]), "r"(b0), "r"(b1));
}
__device__ __forceinline__ void ldsm_x4(uint32_t* r, uint32_t addr) {
    asm volatile("ldmatrix.sync.aligned.m8n8.x4.shared.b16 {%0,%1,%2,%3}, [%4];"
        : "=r"(r[0]), "=r"(r[1]), "=r"(r[2]), "=r"(r[3]) : "r"(addr));
}
__device__ __forceinline__ void ldsm_x4_t(uint32_t* r, uint32_t addr) {
    asm volatile("ldmatrix.sync.aligned.m8n8.x4.trans.shared.b16 {%0,%1,%2,%3}, [%4];"
        : "=r"(r[0]), "=r"(r[1]), "=r"(r[2]), "=r"(r[3]) : "r"(addr));
}

// ---------------- mask bit-packing ----------------
__global__ void pack_mask(const int* __restrict__ mask) {
    int idx = blockIdx.x * 256 + threadIdx.x;
    int val = mask[idx] != 0;
    unsigned bb = __ballot_sync(0xffffffffu, val);
    if ((threadIdx.x & 31) == 0) g_mbits[idx >> 5] = bb;
}

// ---------------- main kernel ----------------
__global__ void __launch_bounds__(NTH)
mha_mma(const float* __restrict__ Q, const float* __restrict__ K,
        const float* __restrict__ V, float* __restrict__ Out)
{
    __shared__ __align__(16) char sm[4 * TILE_B];   // KH, KL, VH, VL
    const uint32_t sKH = smem_u32(sm);
    const uint32_t sKL = sKH + TILE_B;
    const uint32_t sVH = sKL + TILE_B;
    const uint32_t sVL = sVH + TILE_B;

    const int tid  = threadIdx.x;
    const int wid  = tid >> 5;
    const int lane = tid & 31;
    const int g    = lane >> 2;      // 0..7  (row within octet)
    const int tig  = lane & 3;       // 0..3  (col pair)
    const int qt = blockIdx.x, h = blockIdx.y, b = blockIdx.z;
    const int q0 = qt * BM;
    const int wr = wid * 16;         // warp's row base within tile

    const int row0 = q0 + wr + g;    // thread's two query rows
    const int row1 = row0 + 8;

    // ---- load Q fragments from gmem (persistent in regs), split hi/lo ----
    uint32_t qh[4][4], ql[4][4];
    {
        const float* qp = Q + ((size_t)b * S_LEN) * DMODEL + h * HD;
        #pragma unroll
        for (int ks = 0; ks < 4; ks++) {
            int c0 = ks * 16 + 2 * tig;
            #pragma unroll
            for (int fi = 0; fi < 4; fi++) {
                int rrow = (fi & 1) ? row1 : row0;
                int ccol = c0 + ((fi & 2) ? 8 : 0);
                float2 t = *(const float2*)(qp + (size_t)rrow * DMODEL + ccol);
                float h0 = tobf(t.x), h1 = tobf(t.y);
                qh[ks][fi] = pack2(h0, h1);
                ql[ks][fi] = pack2(t.x - h0, t.y - h1);
            }
        }
    }

    float o[8][4];
    #pragma unroll
    for (int dt = 0; dt < 8; dt++)
        #pragma unroll
        for (int j = 0; j < 4; j++) o[dt][j] = 0.f;
    float m_i[2] = {-1e30f, -1e30f}, l_i[2] = {0.f, 0.f};

    const float* kp = K + ((size_t)b * S_LEN) * DMODEL + h * HD;
    const float* vp = V + ((size_t)b * S_LEN) * DMODEL + h * HD;
    const unsigned long long* mb64 = (const unsigned long long*)g_mbits;
    const size_t mrow0 = ((size_t)b * S_LEN + row0) * 32;
    const size_t mrow1 = ((size_t)b * S_LEN + row1) * 32;

    // ldmatrix address helpers (bytes)
    const int l15 = lane & 15;
    const int krow = l15 & 7;               // K: row within octet
    const int kq   = lane >> 3;             // 0..3 -> k offset 8*kq

    for (int kt = 0; kt < NKT; ++kt) {
        const int k0 = kt * BN;
        __syncthreads();   // previous iteration's ldmatrix done

        // ---- cooperative load K,V: fp32 -> split bf16 hi/lo -> smem ----
        #pragma unroll
        for (int u = 0; u < 4; ++u) {
            int idx = tid + u * NTH;             // 0..1023
            int row = idx >> 4, c4 = (idx & 15) << 2;
            uint32_t so = (uint32_t)(row * ROWB + c4 * 2);

            float4 tk = *(const float4*)(kp + (size_t)(k0 + row) * DMODEL + c4);
            float h0 = tobf(tk.x), h1 = tobf(tk.y), h2 = tobf(tk.z), h3 = tobf(tk.w);
            *(uint2*)(sm + (sKH - smem_u32(sm)) + so) =
                make_uint2(pack2(h0, h1), pack2(h2, h3));
            *(uint2*)(sm + (sKL - smem_u32(sm)) + so) =
                make_uint2(pack2(tk.x - h0, tk.y - h1), pack2(tk.z - h2, tk.w - h3));

            float4 tv = *(const float4*)(vp + (size_t)(k0 + row) * DMODEL + c4);
            float v0 = tobf(tv.x), v1 = tobf(tv.y), v2 = tobf(tv.z), v3 = tobf(tv.w);
            *(uint2*)(sm + (sVH - smem_u32(sm)) + so) =
                make_uint2(pack2(v0, v1), pack2(v2, v3));
            *(uint2*)(sm + (sVL - smem_u32(sm)) + so) =
                make_uint2(pack2(tv.x - v0, tv.y - v1), pack2(tv.z - v2, tv.w - v3));
        }
        __syncthreads();

        // ---- GEMM1: S = QhKh + QhKl + QlKh ----
        float s[8][4];
        #pragma unroll
        for (int nt = 0; nt < 8; nt++) {
            #pragma unroll
            for (int j = 0; j < 4; j++) s[nt][j] = 0.f;
            #pragma unroll
            for (int kpair = 0; kpair < 2; kpair++) {
                // addr: rows n0+krow, k columns kpair*32 + kq*8
                uint32_t aoff = (uint32_t)((nt * 8 + krow) * ROWB + (kpair * 32 + kq * 8) * 2);
                uint32_t bh[4], bl[4];
                ldsm_x4(bh, sKH + aoff);
                ldsm_x4(bl, sKL + aoff);
                mma_bf16(s[nt], qh[2 * kpair],     bh[0], bh[1]);
                mma_bf16(s[nt], qh[2 * kpair],     bl[0], bl[1]);
                mma_bf16(s[nt], ql[2 * kpair],     bh[0], bh[1]);
                mma_bf16(s[nt], qh[2 * kpair + 1], bh[2], bh[3]);
                mma_bf16(s[nt], qh[2 * kpair + 1], bl[2], bl[3]);
                mma_bf16(s[nt], ql[2 * kpair + 1], bh[2], bh[3]);
            }
        }

        // ---- mask + online softmax (rows: row0 via c0,c1 ; row1 via c2,c3) ----
        unsigned long long mb0 = mb64[mrow0 + kt];
        unsigned long long mb1 = mb64[mrow1 + kt];
        float mx0 = -1e30f, mx1 = -1e30f;
        #pragma unroll
        for (int nt = 0; nt < 8; nt++) {
            int c0 = nt * 8 + 2 * tig;
            float b00 = ((mb0 >> c0) & 1ull) ? 0.f : -1.0e9f;
            float b01 = ((mb0 >> (c0 + 1)) & 1ull) ? 0.f : -1.0e9f;
            float b10 = ((mb1 >> c0) & 1ull) ? 0.f : -1.0e9f;
            float b11 = ((mb1 >> (c0 + 1)) & 1ull) ? 0.f : -1.0e9f;
            s[nt][0] = s[nt][0] * 0.125f + b00;
            s[nt][1] = s[nt][1] * 0.125f + b01;
            s[nt][2] = s[nt][2] * 0.125f + b10;
            s[nt][3] = s[nt][3] * 0.125f + b11;
            mx0 = fmaxf(mx0, fmaxf(s[nt][0], s[nt][1]));
            mx1 = fmaxf(mx1, fmaxf(s[nt][2], s[nt][3]));
        }
        mx0 = fmaxf(mx0, __shfl_xor_sync(0xffffffffu, mx0, 1));
        mx0 = fmaxf(mx0, __shfl_xor_sync(0xffffffffu, mx0, 2));
        mx1 = fmaxf(mx1, __shfl_xor_sync(0xffffffffu, mx1, 1));
        mx1 = fmaxf(mx1, __shfl_xor_sync(0xffffffffu, mx1, 2));

        float mn0 = fmaxf(m_i[0], mx0), mn1 = fmaxf(m_i[1], mx1);
        float a0 = __expf(m_i[0] - mn0), a1 = __expf(m_i[1] - mn1);
        float sum0 = 0.f, sum1 = 0.f;
        #pragma unroll
        for (int nt = 0; nt < 8; nt++) {
            s[nt][0] = __expf(s[nt][0] - mn0);
            s[nt][1] = __expf(s[nt][1] - mn0);
            s[nt][2] = __expf(s[nt][2] - mn1);
            s[nt][3] = __expf(s[nt][3] - mn1);
            sum0 += s[nt][0] + s[nt][1];
            sum1 += s[nt][2] + s[nt][3];
        }
        sum0 += __shfl_xor_sync(0xffffffffu, sum0, 1);
        sum0 += __shfl_xor_sync(0xffffffffu, sum0, 2);
        sum1 += __shfl_xor_sync(0xffffffffu, sum1, 1);
        sum1 += __shfl_xor_sync(0xffffffffu, sum1, 2);
        l_i[0] = l_i[0] * a0 + sum0;  m_i[0] = mn0;
        l_i[1] = l_i[1] * a1 + sum1;  m_i[1] = mn1;
        #pragma unroll
        for (int dt = 0; dt < 8; dt++) {
            o[dt][0] *= a0; o[dt][1] *= a0;
            o[dt][2] *= a1; o[dt][3] *= a1;
        }

        // ---- P fragments (register-only relayout), split hi/lo ----
        uint32_t ph[4][4], pl[4][4];
        #pragma unroll
        for (int ks = 0; ks < 4; ks++) {
            float p00 = s[2 * ks][0],     p01 = s[2 * ks][1];
            float p10 = s[2 * ks][2],     p11 = s[2 * ks][3];
            float p20 = s[2 * ks + 1][0], p21 = s[2 * ks + 1][1];
            float p30 = s[2 * ks + 1][2], p31 = s[2 * ks + 1][3];
            float h00 = tobf(p00), h01 = tobf(p01), h10 = tobf(p10), h11 = tobf(p11);
            float h20 = tobf(p20), h21 = tobf(p21), h30 = tobf(p30), h31 = tobf(p31);
            ph[ks][0] = pack2(h00, h01); ph[ks][1] = pack2(h10, h11);
            ph[ks][2] = pack2(h20, h21); ph[ks][3] = pack2(h30, h31);
            pl[ks][0] = pack2(p00 - h00, p01 - h01); pl[ks][1] = pack2(p10 - h10, p11 - h11);
            pl[ks][2] = pack2(p20 - h20, p21 - h21); pl[ks][3] = pack2(p30 - h30, p31 - h31);
        }

        // ---- GEMM2: O += PhVh + PhVl + PlVh  (V via ldmatrix.trans) ----
        #pragma unroll
        for (int dt = 0; dt < 8; dt++) {
            #pragma unroll
            for (int kpair = 0; kpair < 2; kpair++) {
                // addr: V rows (keys) kpair*32 + lane, cols dt*8
                uint32_t aoff = (uint32_t)((kpair * 32 + lane) * ROWB + dt * 8 * 2);
                uint32_t vh[4], vl[4];
                ldsm_x4_t(vh, sVH + aoff);
                ldsm_x4_t(vl, sVL + aoff);
                mma_bf16(o[dt], ph[2 * kpair],     vh[0], vh[1]);
                mma_bf16(o[dt], ph[2 * kpair],     vl[0], vl[1]);
                mma_bf16(o[dt], pl[2 * kpair],     vh[0], vh[1]);
                mma_bf16(o[dt], ph[2 * kpair + 1], vh[2], vh[3]);
                mma_bf16(o[dt], ph[2 * kpair + 1], vl[2], vl[3]);
                mma_bf16(o[dt], pl[2 * kpair + 1], vh[2], vh[3]);
            }
        }
    }

    // ---- normalize + write out ----
    {
        float inv0 = 1.f / l_i[0], inv1 = 1.f / l_i[1];
        float* op0 = Out + ((size_t)b * S_LEN + row0) * DMODEL + h * HD;
        float* op1 = Out + ((size_t)b * S_LEN + row1) * DMODEL + h * HD;
        #pragma unroll
        for (int dt = 0; dt < 8; dt++) {
            int c0 = dt * 8 + 2 * tig;
            *(float2*)(op0 + c0) = make_float2(o[dt][0] * inv0, o[dt][1] * inv0);
            *(float2*)(op1 + c0) = make_float2(o[dt][2] * inv1, o[dt][3] * inv1);
        }
    }
}

extern "C" void kernel_launch(void* const* d_in, const int* in_sizes, int n_in,
                              void* d_out, int out_size)
{
    const float* q = (const float*)d_in[0];
    const float* k = (const float*)d_in[1];
    const float* v = (const float*)d_in[2];
    const int* mask = (const int*)d_in[3];
    float* out = (float*)d_out;

    pack_mask<<<BATCH * S_LEN * S_LEN / 256, 256>>>(mask);

    dim3 grid(S_LEN / BM, NHEAD, BATCH);
    mha_mma<<<grid, NTH>>>(q, k, v, out);
}

// round 6
// speedup vs baseline: 2.7164x; 1.2761x over previous
#include <cuda_runtime.h>
#include <cuda_bf16.h>
#include <cstdint>

// MultiHeadAttentionMap: B=2, S=2048, D=1024, H=16, head_dim=64
// R6: HMMA bf16 flash attention; 4 warps x 32 rows/warp (fragment reuse x2),
//     2 CTAs/SM, B/V fragments shared across row-sets.

#define S_LEN 2048
#define DMODEL 1024
#define NHEAD 16
#define BATCH 2
#define HD 64
#define BM 128          // rows per CTA (4 warps x 32)
#define BN 64           // keys per tile
#define NKT (S_LEN / BN)
#define NTH 128

#define ROWB 144        // smem row stride bytes (72 bf16): conflict-free ldmatrix
#define TILE_B (64 * ROWB)   // 9216

__device__ __align__(8) unsigned g_mbits[BATCH * S_LEN * S_LEN / 32];

__device__ __forceinline__ uint32_t smem_u32(const void* p) {
    uint32_t a;
    asm("{ .reg .u64 t; cvta.to.shared.u64 t, %1; cvt.u32.u64 %0, t; }" : "=r"(a) : "l"(p));
    return a;
}
__device__ __forceinline__ uint32_t pack2(float lo, float hi) {
    uint32_t d;
    asm("cvt.rn.bf16x2.f32 %0, %1, %2;" : "=r"(d) : "f"(hi), "f"(lo));
    return d;
}
__device__ __forceinline__ float tobf(float f) {
    return __bfloat162float(__float2bfloat16_rn(f));
}
__device__ __forceinline__ void mma_bf16(float* c, const uint32_t* a, uint32_t b0, uint32_t b1) {
    asm volatile(
        "mma.sync.aligned.m16n8k16.row.col.f32.bf16.bf16.f32 "
        "{%0,%1,%2,%3}, {%4,%5,%6,%7}, {%8,%9}, {%0,%1,%2,%3};"
        : "+f"(c[0]), "+f"(c[1]), "+f"(c[2]), "+f"(c[3])
        : "r"(a[0]), "r"(a[1]), "r"(a[2]), "r"(a[3]), "r"(b0), "r"(b1));
}
__device__ __forceinline__ void ldsm_x4(uint32_t* r, uint32_t addr) {
    asm volatile("ldmatrix.sync.aligned.m8n8.x4.shared.b16 {%0,%1,%2,%3}, [%4];"
        : "=r"(r[0]), "=r"(r[1]), "=r"(r[2]), "=r"(r[3]) : "r"(addr));
}
__device__ __forceinline__ void ldsm_x4_t(uint32_t* r, uint32_t addr) {
    asm volatile("ldmatrix.sync.aligned.m8n8.x4.trans.shared.b16 {%0,%1,%2,%3}, [%4];"
        : "=r"(r[0]), "=r"(r[1]), "=r"(r[2]), "=r"(r[3]) : "r"(addr));
}

// ---------------- mask bit-packing ----------------
__global__ void pack_mask(const int* __restrict__ mask) {
    int idx = blockIdx.x * 256 + threadIdx.x;
    int val = mask[idx] != 0;
    unsigned bb = __ballot_sync(0xffffffffu, val);
    if ((threadIdx.x & 31) == 0) g_mbits[idx >> 5] = bb;
}

// ---------------- main kernel ----------------
__global__ void __launch_bounds__(NTH, 2)
mha_mma(const float* __restrict__ Q, const float* __restrict__ K,
        const float* __restrict__ V, float* __restrict__ Out)
{
    __shared__ __align__(16) char sm[4 * TILE_B];   // KH, KL, VH, VL
    char* pKH = sm;
    char* pKL = sm + TILE_B;
    char* pVH = sm + 2 * TILE_B;
    char* pVL = sm + 3 * TILE_B;
    const uint32_t sKH = smem_u32(pKH);
    const uint32_t sKL = sKH + TILE_B;
    const uint32_t sVH = sKL + TILE_B;
    const uint32_t sVL = sVH + TILE_B;

    const int tid  = threadIdx.x;
    const int wid  = tid >> 5;
    const int lane = tid & 31;
    const int g    = lane >> 2;      // row within octet
    const int tig  = lane & 3;       // col pair
    const int qt = blockIdx.x, h = blockIdx.y, b = blockIdx.z;
    const int q0 = qt * BM;
    const int wr = wid * 32;         // warp row base (32 rows per warp)

    // thread's 4 query rows: [rs][0/1] = q0+wr+rs*16+g (+8)
    int rowg[2][2];
    rowg[0][0] = q0 + wr + g;      rowg[0][1] = rowg[0][0] + 8;
    rowg[1][0] = rowg[0][0] + 16;  rowg[1][1] = rowg[0][0] + 24;

    // ---- Q fragments (persistent), split hi/lo: [rs][kchunk][4] ----
    uint32_t qh[2][4][4], ql[2][4][4];
    {
        const float* qp = Q + ((size_t)b * S_LEN) * DMODEL + h * HD;
        #pragma unroll
        for (int rs = 0; rs < 2; rs++)
            #pragma unroll
            for (int ks = 0; ks < 4; ks++) {
                int c0 = ks * 16 + 2 * tig;
                #pragma unroll
                for (int fi = 0; fi < 4; fi++) {
                    int rrow = rowg[rs][fi & 1];
                    int ccol = c0 + ((fi & 2) ? 8 : 0);
                    float2 t = *(const float2*)(qp + (size_t)rrow * DMODEL + ccol);
                    float h0 = tobf(t.x), h1 = tobf(t.y);
                    qh[rs][ks][fi] = pack2(h0, h1);
                    ql[rs][ks][fi] = pack2(t.x - h0, t.y - h1);
                }
            }
    }

    float o[2][8][4];
    #pragma unroll
    for (int rs = 0; rs < 2; rs++)
        #pragma unroll
        for (int dt = 0; dt < 8; dt++)
            #pragma unroll
            for (int j = 0; j < 4; j++) o[rs][dt][j] = 0.f;
    float m_i[2][2] = {{-1e30f, -1e30f}, {-1e30f, -1e30f}};
    float l_i[2][2] = {{0.f, 0.f}, {0.f, 0.f}};

    const float* kp = K + ((size_t)b * S_LEN) * DMODEL + h * HD;
    const float* vp = V + ((size_t)b * S_LEN) * DMODEL + h * HD;
    const unsigned long long* mb64 = (const unsigned long long*)g_mbits;
    size_t mrow[2][2];
    #pragma unroll
    for (int rs = 0; rs < 2; rs++) {
        mrow[rs][0] = ((size_t)b * S_LEN + rowg[rs][0]) * 32;
        mrow[rs][1] = ((size_t)b * S_LEN + rowg[rs][1]) * 32;
    }

    const int krow = lane & 7;
    const int kq   = lane >> 3;

    for (int kt = 0; kt < NKT; ++kt) {
        const int k0 = kt * BN;
        __syncthreads();

        // ---- cooperative load K,V: fp32 -> split bf16 hi/lo -> smem ----
        #pragma unroll 4
        for (int u = 0; u < 8; ++u) {
            int idx = tid + u * NTH;             // 0..1023
            int row = idx >> 4, c4 = (idx & 15) << 2;
            uint32_t so = (uint32_t)(row * ROWB + c4 * 2);

            float4 tk = *(const float4*)(kp + (size_t)(k0 + row) * DMODEL + c4);
            float h0 = tobf(tk.x), h1 = tobf(tk.y), h2 = tobf(tk.z), h3 = tobf(tk.w);
            *(uint2*)(pKH + so) = make_uint2(pack2(h0, h1), pack2(h2, h3));
            *(uint2*)(pKL + so) = make_uint2(pack2(tk.x - h0, tk.y - h1), pack2(tk.z - h2, tk.w - h3));

            float4 tv = *(const float4*)(vp + (size_t)(k0 + row) * DMODEL + c4);
            float v0 = tobf(tv.x), v1 = tobf(tv.y), v2 = tobf(tv.z), v3 = tobf(tv.w);
            *(uint2*)(pVH + so) = make_uint2(pack2(v0, v1), pack2(v2, v3));
            *(uint2*)(pVL + so) = make_uint2(pack2(tv.x - v0, tv.y - v1), pack2(tv.z - v2, tv.w - v3));
        }
        __syncthreads();

        // ---- GEMM1: S = QhKh + QhKl + QlKh ; B fragments shared by both row-sets ----
        float s[2][8][4];
        #pragma unroll
        for (int rs = 0; rs < 2; rs++)
            #pragma unroll
            for (int nt = 0; nt < 8; nt++)
                #pragma unroll
                for (int j = 0; j < 4; j++) s[rs][nt][j] = 0.f;

        #pragma unroll
        for (int nt = 0; nt < 8; nt++) {
            #pragma unroll
            for (int kpair = 0; kpair < 2; kpair++) {
                uint32_t aoff = (uint32_t)((nt * 8 + krow) * ROWB + (kpair * 32 + kq * 8) * 2);
                uint32_t bh[4], bl[4];
                ldsm_x4(bh, sKH + aoff);
                ldsm_x4(bl, sKL + aoff);
                #pragma unroll
                for (int rs = 0; rs < 2; rs++) {
                    mma_bf16(s[rs][nt], qh[rs][2 * kpair],     bh[0], bh[1]);
                    mma_bf16(s[rs][nt], qh[rs][2 * kpair],     bl[0], bl[1]);
                    mma_bf16(s[rs][nt], ql[rs][2 * kpair],     bh[0], bh[1]);
                    mma_bf16(s[rs][nt], qh[rs][2 * kpair + 1], bh[2], bh[3]);
                    mma_bf16(s[rs][nt], qh[rs][2 * kpair + 1], bl[2], bl[3]);
                    mma_bf16(s[rs][nt], ql[rs][2 * kpair + 1], bh[2], bh[3]);
                }
            }
        }

        // ---- mask + online softmax + P fragments, per row-set ----
        uint32_t ph[2][4][4], pl[2][4][4];
        #pragma unroll
        for (int rs = 0; rs < 2; rs++) {
            unsigned long long mb0 = mb64[mrow[rs][0] + kt];
            unsigned long long mb1 = mb64[mrow[rs][1] + kt];
            float mx0 = -1e30f, mx1 = -1e30f;
            #pragma unroll
            for (int nt = 0; nt < 8; nt++) {
                int c0 = nt * 8 + 2 * tig;
                float b00 = ((mb0 >> c0) & 1ull) ? 0.f : -1.0e9f;
                float b01 = ((mb0 >> (c0 + 1)) & 1ull) ? 0.f : -1.0e9f;
                float b10 = ((mb1 >> c0) & 1ull) ? 0.f : -1.0e9f;
                float b11 = ((mb1 >> (c0 + 1)) & 1ull) ? 0.f : -1.0e9f;
                s[rs][nt][0] = s[rs][nt][0] * 0.125f + b00;
                s[rs][nt][1] = s[rs][nt][1] * 0.125f + b01;
                s[rs][nt][2] = s[rs][nt][2] * 0.125f + b10;
                s[rs][nt][3] = s[rs][nt][3] * 0.125f + b11;
                mx0 = fmaxf(mx0, fmaxf(s[rs][nt][0], s[rs][nt][1]));
                mx1 = fmaxf(mx1, fmaxf(s[rs][nt][2], s[rs][nt][3]));
            }
            mx0 = fmaxf(mx0, __shfl_xor_sync(0xffffffffu, mx0, 1));
            mx0 = fmaxf(mx0, __shfl_xor_sync(0xffffffffu, mx0, 2));
            mx1 = fmaxf(mx1, __shfl_xor_sync(0xffffffffu, mx1, 1));
            mx1 = fmaxf(mx1, __shfl_xor_sync(0xffffffffu, mx1, 2));

            float mn0 = fmaxf(m_i[rs][0], mx0), mn1 = fmaxf(m_i[rs][1], mx1);
            float a0 = __expf(m_i[rs][0] - mn0), a1 = __expf(m_i[rs][1] - mn1);
            float sum0 = 0.f, sum1 = 0.f;
            #pragma unroll
            for (int nt = 0; nt < 8; nt++) {
                s[rs][nt][0] = __expf(s[rs][nt][0] - mn0);
                s[rs][nt][1] = __expf(s[rs][nt][1] - mn0);
                s[rs][nt][2] = __expf(s[rs][nt][2] - mn1);
                s[rs][nt][3] = __expf(s[rs][nt][3] - mn1);
                sum0 += s[rs][nt][0] + s[rs][nt][1];
                sum1 += s[rs][nt][2] + s[rs][nt][3];
            }
            sum0 += __shfl_xor_sync(0xffffffffu, sum0, 1);
            sum0 += __shfl_xor_sync(0xffffffffu, sum0, 2);
            sum1 += __shfl_xor_sync(0xffffffffu, sum1, 1);
            sum1 += __shfl_xor_sync(0xffffffffu, sum1, 2);
            l_i[rs][0] = l_i[rs][0] * a0 + sum0;  m_i[rs][0] = mn0;
            l_i[rs][1] = l_i[rs][1] * a1 + sum1;  m_i[rs][1] = mn1;
            #pragma unroll
            for (int dt = 0; dt < 8; dt++) {
                o[rs][dt][0] *= a0; o[rs][dt][1] *= a0;
                o[rs][dt][2] *= a1; o[rs][dt][3] *= a1;
            }

            // P fragments (register relayout), split hi/lo
            #pragma unroll
            for (int ks = 0; ks < 4; ks++) {
                float p00 = s[rs][2 * ks][0],     p01 = s[rs][2 * ks][1];
                float p10 = s[rs][2 * ks][2],     p11 = s[rs][2 * ks][3];
                float p20 = s[rs][2 * ks + 1][0], p21 = s[rs][2 * ks + 1][1];
                float p30 = s[rs][2 * ks + 1][2], p31 = s[rs][2 * ks + 1][3];
                float h00 = tobf(p00), h01 = tobf(p01), h10 = tobf(p10), h11 = tobf(p11);
                float h20 = tobf(p20), h21 = tobf(p21), h30 = tobf(p30), h31 = tobf(p31);
                ph[rs][ks][0] = pack2(h00, h01); ph[rs][ks][1] = pack2(h10, h11);
                ph[rs][ks][2] = pack2(h20, h21); ph[rs][ks][3] = pack2(h30, h31);
                pl[rs][ks][0] = pack2(p00 - h00, p01 - h01); pl[rs][ks][1] = pack2(p10 - h10, p11 - h11);
                pl[rs][ks][2] = pack2(p20 - h20, p21 - h21); pl[rs][ks][3] = pack2(p30 - h30, p31 - h31);
            }
        }

        // ---- GEMM2: O += PhVh + PhVl + PlVh ; V fragments shared by both row-sets ----
        #pragma unroll
        for (int dt = 0; dt < 8; dt++) {
            #pragma unroll
            for (int kpair = 0; kpair < 2; kpair++) {
                uint32_t aoff = (uint32_t)((kpair * 32 + lane) * ROWB + dt * 8 * 2);
                uint32_t vh[4], vl[4];
                ldsm_x4_t(vh, sVH + aoff);
                ldsm_x4_t(vl, sVL + aoff);
                #pragma unroll
                for (int rs = 0; rs < 2; rs++) {
                    mma_bf16(o[rs][dt], ph[rs][2 * kpair],     vh[0], vh[1]);
                    mma_bf16(o[rs][dt], ph[rs][2 * kpair],     vl[0], vl[1]);
                    mma_bf16(o[rs][dt], pl[rs][2 * kpair],     vh[0], vh[1]);
                    mma_bf16(o[rs][dt], ph[rs][2 * kpair + 1], vh[2], vh[3]);
                    mma_bf16(o[rs][dt], ph[rs][2 * kpair + 1], vl[2], vl[3]);
                    mma_bf16(o[rs][dt], pl[rs][2 * kpair + 1], vh[2], vh[3]);
                }
            }
        }
    }

    // ---- normalize + write out ----
    #pragma unroll
    for (int rs = 0; rs < 2; rs++) {
        float inv0 = 1.f / l_i[rs][0], inv1 = 1.f / l_i[rs][1];
        float* op0 = Out + ((size_t)b * S_LEN + rowg[rs][0]) * DMODEL + h * HD;
        float* op1 = Out + ((size_t)b * S_LEN + rowg[rs][1]) * DMODEL + h * HD;
        #pragma unroll
        for (int dt = 0; dt < 8; dt++) {
            int c0 = dt * 8 + 2 * tig;
            *(float2*)(op0 + c0) = make_float2(o[rs][dt][0] * inv0, o[rs][dt][1] * inv0);
            *(float2*)(op1 + c0) = make_float2(o[rs][dt][2] * inv1, o[rs][dt][3] * inv1);
        }
    }
}

extern "C" void kernel_launch(void* const* d_in, const int* in_sizes, int n_in,
                              void* d_out, int out_size)
{
    const float* q = (const float*)d_in[0];
    const float* k = (const float*)d_in[1];
    const float* v = (const float*)d_in[2];
    const int* mask = (const int*)d_in[3];
    float* out = (float*)d_out;

    pack_mask<<<BATCH * S_LEN * S_LEN / 256, 256>>>(mask);

    dim3 grid(S_LEN / BM, NHEAD, BATCH);
    mha_mma<<<grid, NTH>>>(q, k, v, out);
}